// round 12
// baseline (speedup 1.0000x reference)
#include <cuda_runtime.h>
#include <cstdint>

constexpr int B  = 8192;    // batch
constexpr int D  = 4096;    // features
constexpr int H  = 2048;    // hidden
constexpr int HW = H / 32;  // 64 packed words
constexpr int GRID = 512;   // MUST be <= 148 SMs * 4 CTA/SM (residency guarantee)

// Device-global scratch (no runtime allocation allowed)
__device__ uint32_t g_Wcols[D * HW];     // Wb column d packed along h (1 MB)
__device__ float    g_template[D];       // layer-2 output row for all-ones h
__device__ uint32_t g_m1[HW], g_m2[HW], g_m3[HW], g_m4[HW], g_mall[HW];
__device__ int      g_t2[D];
__device__ int      g_t1u;               // uniform layer-1 threshold in {1,2}, else -1
__device__ unsigned int g_barc[2];       // monotonic ticket-barrier counters

// Replay-safe device-wide barrier: counters only grow; each launch consumes
// exactly GRID tickets per barrier, so target = (ticket/GRID + 1)*GRID works
// for every (serialized) graph replay without any reset.
__device__ __forceinline__ void grid_barrier(int which) {
    __syncthreads();
    if (threadIdx.x == 0) {
        __threadfence();                                   // release our writes
        unsigned int ticket = atomicAdd(&g_barc[which], 1u);
        unsigned int target = (ticket / GRID + 1u) * (unsigned int)GRID;
        while (atomicAdd(&g_barc[which], 0u) < target) { __nanosleep(64); }
        __threadfence();                                   // acquire others' writes
    }
    __syncthreads();
}

// ---------------------------------------------------------------------------
// One persistent kernel: pack -> barrier -> template/t2 -> barrier -> fused.
// ---------------------------------------------------------------------------
__global__ void __launch_bounds__(256, 4) binaps_kernel(const float* __restrict__ x,
                                                        const float* __restrict__ W,
                                                        const float* __restrict__ be,
                                                        const float* __restrict__ b0,
                                                        const float* __restrict__ b3,
                                                        float* __restrict__ out) {
    __shared__ uint32_t sh_h[8][HW];   // fused slow-path h bits (rarely used)
    __shared__ int sflag[8];           // fused per-row template flag
    __shared__ int s_ok;               // block-0 prep
    int tid  = threadIdx.x;
    int warp = tid >> 5;
    int lane = tid & 31;

    // ---- Phase 0 (block 0 only): layer-1 threshold masks + uniformity ----
    if (blockIdx.x == 0) {
        if (tid == 0) s_ok = 1;
        __syncthreads();
        int t0 = (int)ceilf(1.0f - be[0] - b0[0]);
        if (tid < HW) {
            uint32_t m1 = 0, m2 = 0, m3 = 0, m4 = 0, mall = 0;
#pragma unroll
            for (int bit = 0; bit < 32; bit++) {
                int h = tid * 32 + bit;
                int ti = (int)ceilf(1.0f - be[h] - b0[h]);
                uint32_t m = 1u << bit;
                if (ti <= 0)      mall |= m;
                else if (ti == 1) m1 |= m;
                else if (ti == 2) m2 |= m;
                else if (ti == 3) m3 |= m;
                else if (ti == 4) m4 |= m;
            }
            g_m1[tid] = m1; g_m2[tid] = m2; g_m3[tid] = m3; g_m4[tid] = m4; g_mall[tid] = mall;
        }
        int ok = 1;
        for (int h = tid; h < H; h += 256) {
            int ti = (int)ceilf(1.0f - be[h] - b0[h]);
            if (ti != t0) ok = 0;
        }
        if (!ok) s_ok = 0;   // benign race, all writers store 0
        __syncthreads();
        if (tid == 0) g_t1u = (s_ok && t0 >= 1 && t0 <= 2) ? t0 : -1;
    }

    // ---- Phase 1: pack W (round-6 proven pattern, grid-strided) ----
    for (int u = blockIdx.x; u < 2048; u += GRID) {
        int g = u * 256 + tid;       // same indexing as the 12.2us pack
        int part = g >> 12;          // 0..127 : w*2 + half
        int d    = g & (D - 1);      // column, consecutive within warp
        int w    = part >> 1;
        int half = part & 1;
        int h0   = w * 32 + half * 16;

        const float* Wp = W + (size_t)h0 * D + d;
        float fv[16];
#pragma unroll
        for (int r = 0; r < 16; r++)      // batched loads -> high MLP_p1
            fv[r] = __ldcs(Wp + (size_t)r * D);
        uint32_t uw = 0;
#pragma unroll
        for (int r = 0; r < 16; r++)
            if (fv[r] >= 0.5f) uw |= (1u << r);
        reinterpret_cast<uint16_t*>(g_Wcols)[(d * HW + w) * 2 + half] = (uint16_t)uw;
    }

    grid_barrier(0);

    // ---- Phase 2: template + t2 (warp per column, 8 columns per block) ----
    {
        int d = blockIdx.x * 8 + warp;   // 512*8 = 4096 columns
        uint2 v = reinterpret_cast<const uint2*>(g_Wcols + (size_t)d * HW)[lane];
        int c = __popc(v.x) + __popc(v.y);
#pragma unroll
        for (int o = 16; o; o >>= 1) c += __shfl_xor_sync(0xffffffffu, c, o);
        if (lane == 0) {
            int t2 = (int)ceilf(1.0f - b3[d]);
            g_t2[d] = t2;
            g_template[d] = (c >= t2) ? 1.0f : 0.0f;
        }
    }

    grid_barrier(1);

    // ---- Phase 3: fused layer1+layer2 (round-5 proven body), 2 chunks ----
    const float4* tp = reinterpret_cast<const float4*>(g_template);
    float4 tpl0 = tp[tid];
    float4 tpl1 = tp[tid + 256];
    float4 tpl2 = tp[tid + 512];
    float4 tpl3 = tp[tid + 768];
    const uint2* Wc = reinterpret_cast<const uint2*>(g_Wcols);
    int uni = g_t1u;

    for (int chunk = blockIdx.x; chunk < B / 8; chunk += GRID) {
        int b = chunk * 8 + warp;
        const float4* xr = reinterpret_cast<const float4*>(x + (size_t)b * D);

        uint2 c1 = make_uint2(0u, 0u), c2 = make_uint2(0u, 0u);
        uint2 c3 = make_uint2(0u, 0u), c4 = make_uint2(0u, 0u);
        bool sat = false;

        float4 f = xr[lane];                       // prefetch chunk 0
        for (int i = 0; i < 32; i++) {
            float4 cur = f;
            if (i + 1 < 32) f = xr[(i + 1) * 32 + lane];   // prefetch next

            uint32_t mw0 = __ballot_sync(0xffffffffu, cur.x != 0.0f);
            uint32_t mw1 = __ballot_sync(0xffffffffu, cur.y != 0.0f);
            uint32_t mw2 = __ballot_sync(0xffffffffu, cur.z != 0.0f);
            uint32_t mw3 = __ballot_sync(0xffffffffu, cur.w != 0.0f);

            if (uni >= 1) {
#pragma unroll
                for (int j = 0; j < 4; j++) {
                    uint32_t m = (j == 0) ? mw0 : (j == 1) ? mw1 : (j == 2) ? mw2 : mw3;
                    while (m) {
                        int l = __ffs(m) - 1; m &= m - 1;
                        uint2 v = Wc[(i * 128 + l * 4 + j) * 32 + lane];
                        c2.x |= c1.x & v.x; c1.x |= v.x;
                        c2.y |= c1.y & v.y; c1.y |= v.y;
                    }
                }
                uint32_t sw = (uni == 1) ? (c1.x & c1.y) : (c2.x & c2.y);
                if (__all_sync(0xffffffffu, sw == 0xffffffffu)) { sat = true; break; }
            } else {
#pragma unroll
                for (int j = 0; j < 4; j++) {
                    uint32_t m = (j == 0) ? mw0 : (j == 1) ? mw1 : (j == 2) ? mw2 : mw3;
                    while (m) {
                        int l = __ffs(m) - 1; m &= m - 1;
                        uint2 v = Wc[(i * 128 + l * 4 + j) * 32 + lane];
                        c4.x |= c3.x & v.x; c3.x |= c2.x & v.x; c2.x |= c1.x & v.x; c1.x |= v.x;
                        c4.y |= c3.y & v.y; c3.y |= c2.y & v.y; c2.y |= c1.y & v.y; c1.y |= v.y;
                    }
                }
                if (__all_sync(0xffffffffu, (c4.x & c4.y) == 0xffffffffu)) break;
            }
        }

        uint2 hw;
        if (uni >= 1) {
            hw = sat ? make_uint2(0xffffffffu, 0xffffffffu) : ((uni == 1) ? c1 : c2);
        } else {
            int w0 = 2 * lane, w1 = 2 * lane + 1;
            hw.x = g_mall[w0] | (c1.x & g_m1[w0]) | (c2.x & g_m2[w0]) |
                   (c3.x & g_m3[w0]) | (c4.x & g_m4[w0]);
            hw.y = g_mall[w1] | (c1.y & g_m1[w1]) | (c2.y & g_m2[w1]) |
                   (c3.y & g_m3[w1]) | (c4.y & g_m4[w1]);
        }
        bool allones = __all_sync(0xffffffffu, (hw.x & hw.y) == 0xffffffffu);
        if (lane == 0) sflag[warp] = allones ? 1 : 0;

        if (!allones) {
            sh_h[warp][2 * lane]     = hw.x;
            sh_h[warp][2 * lane + 1] = hw.y;
            __syncwarp();
            const uint32_t* hv = sh_h[warp];
            for (int k = 0; k < D / 32; k++) {
                int d = k * 32 + lane;
                int t2 = g_t2[d];
                float val;
                if (t2 <= 0) {
                    val = 1.0f;
                } else {
                    const uint32_t* wv = g_Wcols + (size_t)d * HW;
                    int c = 0;
                    for (int w = 0; w < HW; w++) {
                        c += __popc(hv[w] & wv[w]);
                        if (c >= t2) break;
                    }
                    val = (c >= t2) ? 1.0f : 0.0f;
                }
                out[(size_t)b * D + d] = val;
            }
        }
        __syncthreads();

        // Block-cooperative template broadcast: streaming stores from regs.
#pragma unroll
        for (int r = 0; r < 8; r++) {
            if (sflag[r]) {
                float4* orow = reinterpret_cast<float4*>(out + (size_t)(chunk * 8 + r) * D);
                __stcs(&orow[tid],       tpl0);
                __stcs(&orow[tid + 256], tpl1);
                __stcs(&orow[tid + 512], tpl2);
                __stcs(&orow[tid + 768], tpl3);
            }
        }
        __syncthreads();   // sflag/sh_h reuse safety across chunks
    }
}

// ---------------------------------------------------------------------------
extern "C" void kernel_launch(void* const* d_in, const int* in_sizes, int n_in,
                              void* d_out, int out_size) {
    const float* x     = (const float*)d_in[0];  // [B, D]
    const float* W     = (const float*)d_in[1];  // [H, D]
    const float* b_enc = (const float*)d_in[2];  // [H]
    const float* b0    = (const float*)d_in[3];  // [H]
    const float* b3    = (const float*)d_in[4];  // [D]
    float* out = (float*)d_out;                  // [B, D]

    binaps_kernel<<<GRID, 256>>>(x, W, b_enc, b0, b3, out);
}

// round 13
// speedup vs baseline: 1.0921x; 1.0921x over previous
#include <cuda_runtime.h>
#include <cstdint>

constexpr int B = 8192;    // batch
constexpr int D = 4096;    // features
constexpr int H = 2048;    // hidden
constexpr int HW = H / 32; // 64 packed words

// Device-global scratch (no runtime allocation allowed)
__device__ uint32_t g_Wcols[D * HW];     // Wb column d packed along h (1 MB)
__device__ float    g_template[D];       // layer-2 output row for all-ones h
__device__ uint32_t g_m1[HW], g_m2[HW], g_m3[HW], g_m4[HW], g_mall[HW];
__device__ int      g_t2[D];
__device__ int      g_t1u;               // uniform layer-1 threshold in {1,2}, else -1

// ---------------------------------------------------------------------------
// Kernel 1: pack W.  Tile = 32 columns x 8 words (256 rows).  Warp w owns
// word w0+w for 32 columns: lane = column -> every load step is one coalesced
// 128B line; all 32 loads are batched into fv[] BEFORE any bit logic so
// ptxas keeps them in flight (MLP ~32; round-10's serial fold had MLP ~6).
// Store via smem transpose as 64 uint4 -> Wcols write traffic = 1 MB exactly
// (round-6's 16-bit scattered stores dirtied ~16 MB of sectors).
// ---------------------------------------------------------------------------
__global__ void __launch_bounds__(256) pack_kernel(const float* __restrict__ W) {
    __shared__ uint32_t s[32][9];     // [col][word], padded: conflict-free
    int t    = threadIdx.x;
    int lane = t & 31;
    int warp = t >> 5;
    int tile = blockIdx.x;            // 1024 tiles
    int d0 = (tile & 127) * 32;       // 128 column groups
    int w0 = (tile >> 7) * 8;         // 8 word groups

    const float* Wp = W + (size_t)(w0 + warp) * 32 * D + d0 + lane;
    float fv[32];
#pragma unroll
    for (int r = 0; r < 32; r++)      // 32 independent coalesced loads
        fv[r] = __ldcs(Wp + (size_t)r * D);
    uint32_t u = 0;
#pragma unroll
    for (int r = 0; r < 32; r++)
        if (fv[r] >= 0.5f) u |= (1u << r);
    s[lane][warp] = u;
    __syncthreads();

    if (t < 64) {                     // 64 uint4 = 256 words, full sectors
        int col = t >> 1, j = t & 1;
        uint4 v = make_uint4(s[col][j * 4 + 0], s[col][j * 4 + 1],
                             s[col][j * 4 + 2], s[col][j * 4 + 3]);
        reinterpret_cast<uint4*>(g_Wcols)[(size_t)(d0 + col) * 16 + (w0 >> 2) + j] = v;
    }
}

// ---------------------------------------------------------------------------
// Kernel 2 (prep): blocks 0..15 compute t2 + template per d; block 16 builds
// layer-1 threshold masks and the uniformity flag.
// ---------------------------------------------------------------------------
__global__ void __launch_bounds__(256) prep_kernel(const float* __restrict__ be,
                                                   const float* __restrict__ b0,
                                                   const float* __restrict__ b3) {
    if (blockIdx.x < 16) {
        int d = blockIdx.x * 256 + threadIdx.x;
        int t2 = (int)ceilf(1.0f - b3[d]);
        g_t2[d] = t2;
        const uint4* col = reinterpret_cast<const uint4*>(g_Wcols + (size_t)d * HW);
        int c = 0;
#pragma unroll
        for (int i = 0; i < HW / 4; i++) {
            uint4 v = col[i];
            c += __popc(v.x) + __popc(v.y) + __popc(v.z) + __popc(v.w);
        }
        g_template[d] = (c >= t2) ? 1.0f : 0.0f;
    } else {
        __shared__ int s_ok;
        int t = threadIdx.x;
        if (t == 0) s_ok = 1;
        __syncthreads();

        int t0 = (int)ceilf(1.0f - be[0] - b0[0]);

        if (t < HW) {
            uint32_t m1 = 0, m2 = 0, m3 = 0, m4 = 0, mall = 0;
#pragma unroll
            for (int bit = 0; bit < 32; bit++) {
                int h = t * 32 + bit;
                int ti = (int)ceilf(1.0f - be[h] - b0[h]);
                uint32_t m = 1u << bit;
                if (ti <= 0)      mall |= m;
                else if (ti == 1) m1 |= m;
                else if (ti == 2) m2 |= m;
                else if (ti == 3) m3 |= m;
                else if (ti == 4) m4 |= m;
            }
            g_m1[t] = m1; g_m2[t] = m2; g_m3[t] = m3; g_m4[t] = m4; g_mall[t] = mall;
        }

        int ok = 1;
        for (int h = t; h < H; h += 256) {
            int ti = (int)ceilf(1.0f - be[h] - b0[h]);
            if (ti != t0) ok = 0;
        }
        if (!ok) s_ok = 0;   // benign race, all writers store 0
        __syncthreads();
        if (t == 0) g_t1u = (s_ok && t0 >= 1 && t0 <= 2) ? t0 : -1;
    }
}

// ---------------------------------------------------------------------------
// Kernel 3 (fused layer1+layer2): one warp per batch row, 8 rows per block.
// Proven round-5 version — at its memory floor, unchanged.
// ---------------------------------------------------------------------------
__global__ void __launch_bounds__(256) fused_kernel(const float* __restrict__ x,
                                                    float* __restrict__ out) {
    __shared__ uint32_t sh_h[8][HW];   // slow-path h bits (rarely used)
    __shared__ int sflag[8];           // per-row "broadcast template" flag
    int tid  = threadIdx.x;
    int warp = tid >> 5;
    int lane = tid & 31;
    int b = blockIdx.x * 8 + warp;

    // Preload template slice into registers (prep_kernel already ran).
    const float4* tp = reinterpret_cast<const float4*>(g_template);
    float4 tpl0 = __ldg(&tp[tid]);
    float4 tpl1 = __ldg(&tp[tid + 256]);
    float4 tpl2 = __ldg(&tp[tid + 512]);
    float4 tpl3 = __ldg(&tp[tid + 768]);

    const float4* xr = reinterpret_cast<const float4*>(x + (size_t)b * D);
    const uint2*  Wc = reinterpret_cast<const uint2*>(g_Wcols);
    int uni = g_t1u;

    uint2 c1 = make_uint2(0u, 0u), c2 = make_uint2(0u, 0u);
    uint2 c3 = make_uint2(0u, 0u), c4 = make_uint2(0u, 0u);
    bool sat = false;

    float4 f = xr[lane];                       // prefetch chunk 0
    for (int i = 0; i < 32; i++) {
        float4 cur = f;
        if (i + 1 < 32) f = xr[(i + 1) * 32 + lane];   // prefetch next chunk

        uint32_t mw0 = __ballot_sync(0xffffffffu, cur.x != 0.0f);
        uint32_t mw1 = __ballot_sync(0xffffffffu, cur.y != 0.0f);
        uint32_t mw2 = __ballot_sync(0xffffffffu, cur.z != 0.0f);
        uint32_t mw3 = __ballot_sync(0xffffffffu, cur.w != 0.0f);

        if (uni >= 1) {
            // 2-plane CSA (uniform threshold 1 or 2)
#pragma unroll
            for (int j = 0; j < 4; j++) {
                uint32_t m = (j == 0) ? mw0 : (j == 1) ? mw1 : (j == 2) ? mw2 : mw3;
                while (m) {
                    int l = __ffs(m) - 1; m &= m - 1;
                    uint2 v = Wc[(i * 128 + l * 4 + j) * 32 + lane];
                    c2.x |= c1.x & v.x; c1.x |= v.x;
                    c2.y |= c1.y & v.y; c1.y |= v.y;
                }
            }
            uint32_t sw = (uni == 1) ? (c1.x & c1.y) : (c2.x & c2.y);
            if (__all_sync(0xffffffffu, sw == 0xffffffffu)) { sat = true; break; }
        } else {
            // general 4-plane saturating CSA
#pragma unroll
            for (int j = 0; j < 4; j++) {
                uint32_t m = (j == 0) ? mw0 : (j == 1) ? mw1 : (j == 2) ? mw2 : mw3;
                while (m) {
                    int l = __ffs(m) - 1; m &= m - 1;
                    uint2 v = Wc[(i * 128 + l * 4 + j) * 32 + lane];
                    c4.x |= c3.x & v.x; c3.x |= c2.x & v.x; c2.x |= c1.x & v.x; c1.x |= v.x;
                    c4.y |= c3.y & v.y; c3.y |= c2.y & v.y; c2.y |= c1.y & v.y; c1.y |= v.y;
                }
            }
            if (__all_sync(0xffffffffu, (c4.x & c4.y) == 0xffffffffu)) break;
        }
    }

    // Resolve hidden bits for this row
    uint2 hw;
    if (uni >= 1) {
        hw = sat ? make_uint2(0xffffffffu, 0xffffffffu) : ((uni == 1) ? c1 : c2);
    } else {
        int w0 = 2 * lane, w1 = 2 * lane + 1;
        hw.x = g_mall[w0] | (c1.x & g_m1[w0]) | (c2.x & g_m2[w0]) |
               (c3.x & g_m3[w0]) | (c4.x & g_m4[w0]);
        hw.y = g_mall[w1] | (c1.y & g_m1[w1]) | (c2.y & g_m2[w1]) |
               (c3.y & g_m3[w1]) | (c4.y & g_m4[w1]);
    }
    bool allones = __all_sync(0xffffffffu, (hw.x & hw.y) == 0xffffffffu);
    if (lane == 0) sflag[warp] = allones ? 1 : 0;

    if (!allones) {
        // exact path (rare): popcount h against every Wb column
        sh_h[warp][2 * lane]     = hw.x;
        sh_h[warp][2 * lane + 1] = hw.y;
        __syncwarp();
        const uint32_t* hv = sh_h[warp];
        for (int k = 0; k < D / 32; k++) {
            int d = k * 32 + lane;
            int t2 = g_t2[d];
            float val;
            if (t2 <= 0) {
                val = 1.0f;
            } else {
                const uint32_t* wv = g_Wcols + (size_t)d * HW;
                int c = 0;
                for (int w = 0; w < HW; w++) {
                    c += __popc(hv[w] & wv[w]);
                    if (c >= t2) break;
                }
                val = (c >= t2) ? 1.0f : 0.0f;
            }
            out[(size_t)b * D + d] = val;
        }
    }
    __syncthreads();

    // Block-cooperative template broadcast: pure streaming stores from regs.
#pragma unroll
    for (int r = 0; r < 8; r++) {
        if (sflag[r]) {
            float4* orow = reinterpret_cast<float4*>(out + (size_t)(blockIdx.x * 8 + r) * D);
            __stcs(&orow[tid],       tpl0);
            __stcs(&orow[tid + 256], tpl1);
            __stcs(&orow[tid + 512], tpl2);
            __stcs(&orow[tid + 768], tpl3);
        }
    }
}

// ---------------------------------------------------------------------------
extern "C" void kernel_launch(void* const* d_in, const int* in_sizes, int n_in,
                              void* d_out, int out_size) {
    const float* x     = (const float*)d_in[0];  // [B, D]
    const float* W     = (const float*)d_in[1];  // [H, D]
    const float* b_enc = (const float*)d_in[2];  // [H]
    const float* b0    = (const float*)d_in[3];  // [H]
    const float* b3    = (const float*)d_in[4];  // [D]
    float* out = (float*)d_out;                  // [B, D]

    pack_kernel<<<1024, 256>>>(W);
    prep_kernel<<<17, 256>>>(b_enc, b0, b3);
    fused_kernel<<<B / 8, 256>>>(x, out);
}

// round 14
// speedup vs baseline: 1.2464x; 1.1412x over previous
#include <cuda_runtime.h>
#include <cstdint>

constexpr int B = 8192;    // batch
constexpr int D = 4096;    // features
constexpr int H = 2048;    // hidden
constexpr int HW = H / 32; // 64 packed words

// Device-global scratch (no runtime allocation allowed)
__device__ uint32_t g_Wcols[D * HW];     // Wb column d packed along h (1 MB)
__device__ float    g_template[D];       // layer-2 output row for all-ones h
__device__ uint32_t g_m1[HW], g_m2[HW], g_m3[HW], g_m4[HW], g_mall[HW];
__device__ int      g_t2[D];
__device__ int      g_t1u;               // uniform layer-1 threshold in {1,2}, else -1

// ---------------------------------------------------------------------------
// Kernel 1: pack W + template + t2 (blocks 0..127) and masks/t1u (block 128).
// Tile = 32 columns x FULL 64 words (2048 rows), 512 threads: warp wg owns
// words wg*4..wg*4+3, lane = column (every load step = one coalesced 128B
// line).  Loads batched into fv[32] before bit logic (round-13-proven MLP).
// Because the whole column lives in this block's smem, per-column popcount
// (the all-ones template) is computed here too — prep kernel eliminated.
// ---------------------------------------------------------------------------
__global__ void __launch_bounds__(512) pack_kernel(const float* __restrict__ W,
                                                   const float* __restrict__ be,
                                                   const float* __restrict__ b0,
                                                   const float* __restrict__ b3) {
    if (blockIdx.x < 128) {
        __shared__ uint32_t s[32][65];    // [col][word], stride 65: conflict-free
        __shared__ int scnt[32][16];      // per-col popc partials per warp
        int t    = threadIdx.x;
        int lane = t & 31;                // column
        int wg   = t >> 5;                // warp 0..15, owns words wg*4..wg*4+3
        int d0   = blockIdx.x * 32;

        int pcnt = 0;
#pragma unroll
        for (int k = 0; k < 4; k++) {
            int w = wg * 4 + k;           // word index, rows w*32..w*32+31
            const float* Wp = W + (size_t)(w * 32) * D + d0 + lane;
            float fv[32];
#pragma unroll
            for (int r = 0; r < 32; r++)  // 32 independent coalesced loads
                fv[r] = __ldcs(Wp + (size_t)r * D);
            uint32_t u = 0;
#pragma unroll
            for (int r = 0; r < 32; r++)
                if (fv[r] >= 0.5f) u |= (1u << r);
            s[lane][w] = u;
            pcnt += __popc(u);
        }
        scnt[lane][wg] = pcnt;
        __syncthreads();

        // Store Wcols: 512 threads write 512 uint4 (scalar smem reads, full
        // 32-bit-aligned global sectors -> write traffic = 1 MB exactly).
        {
            int col = t >> 4, j = t & 15;
            uint4 v = make_uint4(s[col][j * 4 + 0], s[col][j * 4 + 1],
                                 s[col][j * 4 + 2], s[col][j * 4 + 3]);
            reinterpret_cast<uint4*>(g_Wcols)[(size_t)(d0 + col) * 16 + j] = v;
        }

        // Template + t2 for this block's 32 columns.
        if (t < 32) {
            int c = 0;
#pragma unroll
            for (int wgi = 0; wgi < 16; wgi++) c += scnt[t][wgi];
            int d = d0 + t;
            int t2 = (int)ceilf(1.0f - b3[d]);
            g_t2[d] = t2;
            g_template[d] = (c >= t2) ? 1.0f : 0.0f;
        }
    } else {
        // Block 128: layer-1 threshold masks + uniformity flag.
        __shared__ int s_ok;
        int t = threadIdx.x;
        if (t == 0) s_ok = 1;
        __syncthreads();

        int t0 = (int)ceilf(1.0f - be[0] - b0[0]);

        if (t < HW) {
            uint32_t m1 = 0, m2 = 0, m3 = 0, m4 = 0, mall = 0;
#pragma unroll
            for (int bit = 0; bit < 32; bit++) {
                int h = t * 32 + bit;
                int ti = (int)ceilf(1.0f - be[h] - b0[h]);
                uint32_t m = 1u << bit;
                if (ti <= 0)      mall |= m;
                else if (ti == 1) m1 |= m;
                else if (ti == 2) m2 |= m;
                else if (ti == 3) m3 |= m;
                else if (ti == 4) m4 |= m;
            }
            g_m1[t] = m1; g_m2[t] = m2; g_m3[t] = m3; g_m4[t] = m4; g_mall[t] = mall;
        }

        int ok = 1;
        for (int h = t; h < H; h += 512) {
            int ti = (int)ceilf(1.0f - be[h] - b0[h]);
            if (ti != t0) ok = 0;
        }
        if (!ok) s_ok = 0;   // benign race, all writers store 0
        __syncthreads();
        if (t == 0) g_t1u = (s_ok && t0 >= 1 && t0 <= 2) ? t0 : -1;
    }
}

// ---------------------------------------------------------------------------
// Kernel 2 (fused layer1+layer2): one warp per batch row, 8 rows per block.
// Proven round-5/13 version — at its memory floor, unchanged.
// ---------------------------------------------------------------------------
__global__ void __launch_bounds__(256) fused_kernel(const float* __restrict__ x,
                                                    float* __restrict__ out) {
    __shared__ uint32_t sh_h[8][HW];   // slow-path h bits (rarely used)
    __shared__ int sflag[8];           // per-row "broadcast template" flag
    int tid  = threadIdx.x;
    int warp = tid >> 5;
    int lane = tid & 31;
    int b = blockIdx.x * 8 + warp;

    // Preload template slice into registers (pack_kernel already ran).
    const float4* tp = reinterpret_cast<const float4*>(g_template);
    float4 tpl0 = __ldg(&tp[tid]);
    float4 tpl1 = __ldg(&tp[tid + 256]);
    float4 tpl2 = __ldg(&tp[tid + 512]);
    float4 tpl3 = __ldg(&tp[tid + 768]);

    const float4* xr = reinterpret_cast<const float4*>(x + (size_t)b * D);
    const uint2*  Wc = reinterpret_cast<const uint2*>(g_Wcols);
    int uni = g_t1u;

    uint2 c1 = make_uint2(0u, 0u), c2 = make_uint2(0u, 0u);
    uint2 c3 = make_uint2(0u, 0u), c4 = make_uint2(0u, 0u);
    bool sat = false;

    float4 f = xr[lane];                       // prefetch chunk 0
    for (int i = 0; i < 32; i++) {
        float4 cur = f;
        if (i + 1 < 32) f = xr[(i + 1) * 32 + lane];   // prefetch next chunk

        uint32_t mw0 = __ballot_sync(0xffffffffu, cur.x != 0.0f);
        uint32_t mw1 = __ballot_sync(0xffffffffu, cur.y != 0.0f);
        uint32_t mw2 = __ballot_sync(0xffffffffu, cur.z != 0.0f);
        uint32_t mw3 = __ballot_sync(0xffffffffu, cur.w != 0.0f);

        if (uni >= 1) {
            // 2-plane CSA (uniform threshold 1 or 2)
#pragma unroll
            for (int j = 0; j < 4; j++) {
                uint32_t m = (j == 0) ? mw0 : (j == 1) ? mw1 : (j == 2) ? mw2 : mw3;
                while (m) {
                    int l = __ffs(m) - 1; m &= m - 1;
                    uint2 v = Wc[(i * 128 + l * 4 + j) * 32 + lane];
                    c2.x |= c1.x & v.x; c1.x |= v.x;
                    c2.y |= c1.y & v.y; c1.y |= v.y;
                }
            }
            uint32_t sw = (uni == 1) ? (c1.x & c1.y) : (c2.x & c2.y);
            if (__all_sync(0xffffffffu, sw == 0xffffffffu)) { sat = true; break; }
        } else {
            // general 4-plane saturating CSA
#pragma unroll
            for (int j = 0; j < 4; j++) {
                uint32_t m = (j == 0) ? mw0 : (j == 1) ? mw1 : (j == 2) ? mw2 : mw3;
                while (m) {
                    int l = __ffs(m) - 1; m &= m - 1;
                    uint2 v = Wc[(i * 128 + l * 4 + j) * 32 + lane];
                    c4.x |= c3.x & v.x; c3.x |= c2.x & v.x; c2.x |= c1.x & v.x; c1.x |= v.x;
                    c4.y |= c3.y & v.y; c3.y |= c2.y & v.y; c2.y |= c1.y & v.y; c1.y |= v.y;
                }
            }
            if (__all_sync(0xffffffffu, (c4.x & c4.y) == 0xffffffffu)) break;
        }
    }

    // Resolve hidden bits for this row
    uint2 hw;
    if (uni >= 1) {
        hw = sat ? make_uint2(0xffffffffu, 0xffffffffu) : ((uni == 1) ? c1 : c2);
    } else {
        int w0 = 2 * lane, w1 = 2 * lane + 1;
        hw.x = g_mall[w0] | (c1.x & g_m1[w0]) | (c2.x & g_m2[w0]) |
               (c3.x & g_m3[w0]) | (c4.x & g_m4[w0]);
        hw.y = g_mall[w1] | (c1.y & g_m1[w1]) | (c2.y & g_m2[w1]) |
               (c3.y & g_m3[w1]) | (c4.y & g_m4[w1]);
    }
    bool allones = __all_sync(0xffffffffu, (hw.x & hw.y) == 0xffffffffu);
    if (lane == 0) sflag[warp] = allones ? 1 : 0;

    if (!allones) {
        // exact path (rare): popcount h against every Wb column
        sh_h[warp][2 * lane]     = hw.x;
        sh_h[warp][2 * lane + 1] = hw.y;
        __syncwarp();
        const uint32_t* hv = sh_h[warp];
        for (int k = 0; k < D / 32; k++) {
            int d = k * 32 + lane;
            int t2 = g_t2[d];
            float val;
            if (t2 <= 0) {
                val = 1.0f;
            } else {
                const uint32_t* wv = g_Wcols + (size_t)d * HW;
                int c = 0;
                for (int w = 0; w < HW; w++) {
                    c += __popc(hv[w] & wv[w]);
                    if (c >= t2) break;
                }
                val = (c >= t2) ? 1.0f : 0.0f;
            }
            out[(size_t)b * D + d] = val;
        }
    }
    __syncthreads();

    // Block-cooperative template broadcast: pure streaming stores from regs.
#pragma unroll
    for (int r = 0; r < 8; r++) {
        if (sflag[r]) {
            float4* orow = reinterpret_cast<float4*>(out + (size_t)(blockIdx.x * 8 + r) * D);
            __stcs(&orow[tid],       tpl0);
            __stcs(&orow[tid + 256], tpl1);
            __stcs(&orow[tid + 512], tpl2);
            __stcs(&orow[tid + 768], tpl3);
        }
    }
}

// ---------------------------------------------------------------------------
extern "C" void kernel_launch(void* const* d_in, const int* in_sizes, int n_in,
                              void* d_out, int out_size) {
    const float* x     = (const float*)d_in[0];  // [B, D]
    const float* W     = (const float*)d_in[1];  // [H, D]
    const float* b_enc = (const float*)d_in[2];  // [H]
    const float* b0    = (const float*)d_in[3];  // [H]
    const float* b3    = (const float*)d_in[4];  // [D]
    float* out = (float*)d_out;                  // [B, D]

    pack_kernel<<<129, 512>>>(W, b_enc, b0, b3);
    fused_kernel<<<B / 8, 256>>>(x, out);
}

// round 15
// speedup vs baseline: 1.3246x; 1.0628x over previous
#include <cuda_runtime.h>
#include <cstdint>

constexpr int B = 8192;    // batch
constexpr int D = 4096;    // features
constexpr int H = 2048;    // hidden
constexpr int HW = H / 32; // 64 packed words

// Device-global scratch (no runtime allocation allowed)
__device__ uint32_t g_Wcols[D * HW];     // Wb column d packed along h (1 MB)
__device__ float    g_template[D];       // layer-2 output row for all-ones h
__device__ uint32_t g_m1[HW], g_m2[HW], g_m3[HW], g_m4[HW], g_mall[HW];
__device__ int      g_t2[D];
__device__ int      g_t1u;               // uniform layer-1 threshold in {1,2}, else -1

// ---------------------------------------------------------------------------
// Kernel 1: pack W + template + t2 (blocks 0..127) and masks/t1u (block 128).
// (Round-14 proven version, unchanged.)
// ---------------------------------------------------------------------------
__global__ void __launch_bounds__(512) pack_kernel(const float* __restrict__ W,
                                                   const float* __restrict__ be,
                                                   const float* __restrict__ b0,
                                                   const float* __restrict__ b3) {
    if (blockIdx.x < 128) {
        __shared__ uint32_t s[32][65];    // [col][word], stride 65: conflict-free
        __shared__ int scnt[32][16];      // per-col popc partials per warp
        int t    = threadIdx.x;
        int lane = t & 31;                // column
        int wg   = t >> 5;                // warp 0..15, owns words wg*4..wg*4+3
        int d0   = blockIdx.x * 32;

        int pcnt = 0;
#pragma unroll
        for (int k = 0; k < 4; k++) {
            int w = wg * 4 + k;           // word index, rows w*32..w*32+31
            const float* Wp = W + (size_t)(w * 32) * D + d0 + lane;
            float fv[32];
#pragma unroll
            for (int r = 0; r < 32; r++)  // 32 independent coalesced loads
                fv[r] = __ldcs(Wp + (size_t)r * D);
            uint32_t u = 0;
#pragma unroll
            for (int r = 0; r < 32; r++)
                if (fv[r] >= 0.5f) u |= (1u << r);
            s[lane][w] = u;
            pcnt += __popc(u);
        }
        scnt[lane][wg] = pcnt;
        __syncthreads();

        // Store Wcols: 512 threads write 512 uint4 (full-sector writes, 1 MB).
        {
            int col = t >> 4, j = t & 15;
            uint4 v = make_uint4(s[col][j * 4 + 0], s[col][j * 4 + 1],
                                 s[col][j * 4 + 2], s[col][j * 4 + 3]);
            reinterpret_cast<uint4*>(g_Wcols)[(size_t)(d0 + col) * 16 + j] = v;
        }

        // Template + t2 for this block's 32 columns.
        if (t < 32) {
            int c = 0;
#pragma unroll
            for (int wgi = 0; wgi < 16; wgi++) c += scnt[t][wgi];
            int d = d0 + t;
            int t2 = (int)ceilf(1.0f - b3[d]);
            g_t2[d] = t2;
            g_template[d] = (c >= t2) ? 1.0f : 0.0f;
        }
    } else {
        // Block 128: layer-1 threshold masks + uniformity flag.
        __shared__ int s_ok;
        int t = threadIdx.x;
        if (t == 0) s_ok = 1;
        __syncthreads();

        int t0 = (int)ceilf(1.0f - be[0] - b0[0]);

        if (t < HW) {
            uint32_t m1 = 0, m2 = 0, m3 = 0, m4 = 0, mall = 0;
#pragma unroll
            for (int bit = 0; bit < 32; bit++) {
                int h = t * 32 + bit;
                int ti = (int)ceilf(1.0f - be[h] - b0[h]);
                uint32_t m = 1u << bit;
                if (ti <= 0)      mall |= m;
                else if (ti == 1) m1 |= m;
                else if (ti == 2) m2 |= m;
                else if (ti == 3) m3 |= m;
                else if (ti == 4) m4 |= m;
            }
            g_m1[t] = m1; g_m2[t] = m2; g_m3[t] = m3; g_m4[t] = m4; g_mall[t] = mall;
        }

        int ok = 1;
        for (int h = t; h < H; h += 512) {
            int ti = (int)ceilf(1.0f - be[h] - b0[h]);
            if (ti != t0) ok = 0;
        }
        if (!ok) s_ok = 0;   // benign race, all writers store 0
        __syncthreads();
        if (t == 0) g_t1u = (s_ok && t0 >= 1 && t0 <= 2) ? t0 : -1;
    }
}

// ---------------------------------------------------------------------------
// Kernel 2 (fused layer1+layer2): one warp per batch row, 8 rows per block.
// NEW: inner CSA loop takes one set bit from EACH of the 4 ballot masks per
// iteration -> 4 independent Wcols loads in flight (MLP 4) instead of a
// serial 1-load dependent chain (the round-13 pack lesson applied here).
// ---------------------------------------------------------------------------
__global__ void __launch_bounds__(256) fused_kernel(const float* __restrict__ x,
                                                    float* __restrict__ out) {
    __shared__ uint32_t sh_h[8][HW];   // slow-path h bits (rarely used)
    __shared__ int sflag[8];           // per-row "broadcast template" flag
    int tid  = threadIdx.x;
    int warp = tid >> 5;
    int lane = tid & 31;
    int b = blockIdx.x * 8 + warp;

    // Preload template slice into registers (pack_kernel already ran).
    const float4* tp = reinterpret_cast<const float4*>(g_template);
    float4 tpl0 = __ldg(&tp[tid]);
    float4 tpl1 = __ldg(&tp[tid + 256]);
    float4 tpl2 = __ldg(&tp[tid + 512]);
    float4 tpl3 = __ldg(&tp[tid + 768]);

    const float4* xr = reinterpret_cast<const float4*>(x + (size_t)b * D);
    const uint2*  Wc = reinterpret_cast<const uint2*>(g_Wcols);
    int uni = g_t1u;

    uint2 c1 = make_uint2(0u, 0u), c2 = make_uint2(0u, 0u);
    uint2 c3 = make_uint2(0u, 0u), c4 = make_uint2(0u, 0u);
    bool sat = false;

    float4 f = xr[lane];                       // prefetch chunk 0
    for (int i = 0; i < 32; i++) {
        float4 cur = f;
        if (i + 1 < 32) f = xr[(i + 1) * 32 + lane];   // prefetch next chunk

        uint32_t mw0 = __ballot_sync(0xffffffffu, cur.x != 0.0f);
        uint32_t mw1 = __ballot_sync(0xffffffffu, cur.y != 0.0f);
        uint32_t mw2 = __ballot_sync(0xffffffffu, cur.z != 0.0f);
        uint32_t mw3 = __ballot_sync(0xffffffffu, cur.w != 0.0f);
        int base = i * 128;

        if (uni >= 1) {
            // 2-plane CSA; 4 predicated independent loads per iteration.
            while (mw0 | mw1 | mw2 | mw3) {
                bool p0 = mw0 != 0, p1 = mw1 != 0, p2 = mw2 != 0, p3 = mw3 != 0;
                uint2 v0, v1, v2, v3;
                if (p0) { int l = __ffs(mw0) - 1; mw0 &= mw0 - 1;
                          v0 = Wc[(base + l * 4 + 0) * 32 + lane]; }
                if (p1) { int l = __ffs(mw1) - 1; mw1 &= mw1 - 1;
                          v1 = Wc[(base + l * 4 + 1) * 32 + lane]; }
                if (p2) { int l = __ffs(mw2) - 1; mw2 &= mw2 - 1;
                          v2 = Wc[(base + l * 4 + 2) * 32 + lane]; }
                if (p3) { int l = __ffs(mw3) - 1; mw3 &= mw3 - 1;
                          v3 = Wc[(base + l * 4 + 3) * 32 + lane]; }
                if (p0) { c2.x |= c1.x & v0.x; c1.x |= v0.x;
                          c2.y |= c1.y & v0.y; c1.y |= v0.y; }
                if (p1) { c2.x |= c1.x & v1.x; c1.x |= v1.x;
                          c2.y |= c1.y & v1.y; c1.y |= v1.y; }
                if (p2) { c2.x |= c1.x & v2.x; c1.x |= v2.x;
                          c2.y |= c1.y & v2.y; c1.y |= v2.y; }
                if (p3) { c2.x |= c1.x & v3.x; c1.x |= v3.x;
                          c2.y |= c1.y & v3.y; c1.y |= v3.y; }
            }
            uint32_t sw = (uni == 1) ? (c1.x & c1.y) : (c2.x & c2.y);
            if (__all_sync(0xffffffffu, sw == 0xffffffffu)) { sat = true; break; }
        } else {
            // general 4-plane saturating CSA, same batched-load structure
            while (mw0 | mw1 | mw2 | mw3) {
                bool p0 = mw0 != 0, p1 = mw1 != 0, p2 = mw2 != 0, p3 = mw3 != 0;
                uint2 v0, v1, v2, v3;
                if (p0) { int l = __ffs(mw0) - 1; mw0 &= mw0 - 1;
                          v0 = Wc[(base + l * 4 + 0) * 32 + lane]; }
                if (p1) { int l = __ffs(mw1) - 1; mw1 &= mw1 - 1;
                          v1 = Wc[(base + l * 4 + 1) * 32 + lane]; }
                if (p2) { int l = __ffs(mw2) - 1; mw2 &= mw2 - 1;
                          v2 = Wc[(base + l * 4 + 2) * 32 + lane]; }
                if (p3) { int l = __ffs(mw3) - 1; mw3 &= mw3 - 1;
                          v3 = Wc[(base + l * 4 + 3) * 32 + lane]; }
                if (p0) { c4.x |= c3.x & v0.x; c3.x |= c2.x & v0.x; c2.x |= c1.x & v0.x; c1.x |= v0.x;
                          c4.y |= c3.y & v0.y; c3.y |= c2.y & v0.y; c2.y |= c1.y & v0.y; c1.y |= v0.y; }
                if (p1) { c4.x |= c3.x & v1.x; c3.x |= c2.x & v1.x; c2.x |= c1.x & v1.x; c1.x |= v1.x;
                          c4.y |= c3.y & v1.y; c3.y |= c2.y & v1.y; c2.y |= c1.y & v1.y; c1.y |= v1.y; }
                if (p2) { c4.x |= c3.x & v2.x; c3.x |= c2.x & v2.x; c2.x |= c1.x & v2.x; c1.x |= v2.x;
                          c4.y |= c3.y & v2.y; c3.y |= c2.y & v2.y; c2.y |= c1.y & v2.y; c1.y |= v2.y; }
                if (p3) { c4.x |= c3.x & v3.x; c3.x |= c2.x & v3.x; c2.x |= c1.x & v3.x; c1.x |= v3.x;
                          c4.y |= c3.y & v3.y; c3.y |= c2.y & v3.y; c2.y |= c1.y & v3.y; c1.y |= v3.y; }
            }
            if (__all_sync(0xffffffffu, (c4.x & c4.y) == 0xffffffffu)) break;
        }
    }

    // Resolve hidden bits for this row
    uint2 hw;
    if (uni >= 1) {
        hw = sat ? make_uint2(0xffffffffu, 0xffffffffu) : ((uni == 1) ? c1 : c2);
    } else {
        int w0 = 2 * lane, w1 = 2 * lane + 1;
        hw.x = g_mall[w0] | (c1.x & g_m1[w0]) | (c2.x & g_m2[w0]) |
               (c3.x & g_m3[w0]) | (c4.x & g_m4[w0]);
        hw.y = g_mall[w1] | (c1.y & g_m1[w1]) | (c2.y & g_m2[w1]) |
               (c3.y & g_m3[w1]) | (c4.y & g_m4[w1]);
    }
    bool allones = __all_sync(0xffffffffu, (hw.x & hw.y) == 0xffffffffu);
    if (lane == 0) sflag[warp] = allones ? 1 : 0;

    if (!allones) {
        // exact path (rare): popcount h against every Wb column
        sh_h[warp][2 * lane]     = hw.x;
        sh_h[warp][2 * lane + 1] = hw.y;
        __syncwarp();
        const uint32_t* hv = sh_h[warp];
        for (int k = 0; k < D / 32; k++) {
            int d = k * 32 + lane;
            int t2 = g_t2[d];
            float val;
            if (t2 <= 0) {
                val = 1.0f;
            } else {
                const uint32_t* wv = g_Wcols + (size_t)d * HW;
                int c = 0;
                for (int w = 0; w < HW; w++) {
                    c += __popc(hv[w] & wv[w]);
                    if (c >= t2) break;
                }
                val = (c >= t2) ? 1.0f : 0.0f;
            }
            out[(size_t)b * D + d] = val;
        }
    }
    __syncthreads();

    // Block-cooperative template broadcast: pure streaming stores from regs.
#pragma unroll
    for (int r = 0; r < 8; r++) {
        if (sflag[r]) {
            float4* orow = reinterpret_cast<float4*>(out + (size_t)(blockIdx.x * 8 + r) * D);
            __stcs(&orow[tid],       tpl0);
            __stcs(&orow[tid + 256], tpl1);
            __stcs(&orow[tid + 512], tpl2);
            __stcs(&orow[tid + 768], tpl3);
        }
    }
}

// ---------------------------------------------------------------------------
extern "C" void kernel_launch(void* const* d_in, const int* in_sizes, int n_in,
                              void* d_out, int out_size) {
    const float* x     = (const float*)d_in[0];  // [B, D]
    const float* W     = (const float*)d_in[1];  // [H, D]
    const float* b_enc = (const float*)d_in[2];  // [H]
    const float* b0    = (const float*)d_in[3];  // [H]
    const float* b3    = (const float*)d_in[4];  // [D]
    float* out = (float*)d_out;                  // [B, D]

    pack_kernel<<<129, 512>>>(W, b_enc, b0, b3);
    fused_kernel<<<B / 8, 256>>>(x, out);
}